// round 16
// baseline (speedup 1.0000x reference)
#include <cuda_runtime.h>
#include <cuda_bf16.h>
#include <cstdint>

#define BB   1024
#define TT   256
#define CC   384
#define HS   64

// Scratch (device globals: allocation-free). Layouts as in R13:
// QfG: Q*SCALE2, tf32-RNA, row-major. KfG: hs pair-packed within 8.
// VtfG: V^T with t pair-packed within 8. WpG: W pair-packed.
__device__ __align__(16) float QfG[BB * TT * HS];
__device__ __align__(16) float KfG[BB * TT * HS];
__device__ __align__(16) float VtfG[BB * HS * TT];
__device__ __align__(16) float WpG[384 * 192];

// ---------------- helpers ----------------
__device__ __forceinline__ uint32_t smem_u32(const void* p) {
    uint32_t a;
    asm("{ .reg .u64 t; cvta.to.shared.u64 t, %1; cvt.u32.u64 %0, t; }" : "=r"(a) : "l"(p));
    return a;
}
__device__ __forceinline__ void cp16(uint32_t dst, const void* src) {
    asm volatile("cp.async.ca.shared.global [%0], [%1], 16;" :: "r"(dst), "l"(src) : "memory");
}
#define CP_COMMIT() asm volatile("cp.async.commit_group;" ::: "memory")
#define CP_WAIT1()  asm volatile("cp.async.wait_group 1;" ::: "memory")
#define CP_WAIT0()  asm volatile("cp.async.wait_group 0;" ::: "memory")

__device__ __forceinline__ uint32_t rna_tf32(uint32_t x) {
    uint32_t r;
    asm("cvt.rna.tf32.f32 %0, %1;" : "=r"(r) : "r"(x));
    return r;
}
__device__ __forceinline__ float rna_tf32_f(float x) {
    float r;
    asm("cvt.rna.tf32.f32 %0, %1;" : "=f"(r) : "f"(x));
    return r;
}
__device__ __forceinline__ float ex2f(float x) {
    float r;
    asm("ex2.approx.f32 %0, %1;" : "=f"(r) : "f"(x));
    return r;
}
#define SCALE2 0.18033688f   // 0.125 * log2(e)

__device__ __forceinline__ int pk8(int h) {
    return (h & ~7) + (h & 3) * 2 + ((h >> 2) & 1);
}

__device__ __forceinline__ void mma16808t(float* c,
                                          uint32_t a0, uint32_t a1, uint32_t a2, uint32_t a3,
                                          uint32_t b0, uint32_t b1) {
    asm volatile(
        "mma.sync.aligned.m16n8k8.row.col.f32.tf32.tf32.f32 "
        "{%0,%1,%2,%3}, {%4,%5,%6,%7}, {%8,%9}, {%0,%1,%2,%3};"
        : "+f"(c[0]), "+f"(c[1]), "+f"(c[2]), "+f"(c[3])
        : "r"(a0), "r"(a1), "r"(a2), "r"(a3), "r"(b0), "r"(b1));
}

// ============================================================================
// Kernel 0: pack W pairs (tf32-RNA): ((k>>3)*4+(k&3))*192+n, half=(k>>2)&1.
// ============================================================================
__global__ void prep_w(const float* __restrict__ Wq,
                       const float* __restrict__ Wk,
                       const float* __restrict__ Wv)
{
    int idx = blockIdx.x * blockDim.x + threadIdx.x;
    if (idx >= 384 * 192) return;
    int k = idx / 192;
    int n = idx % 192;
    int m = n >> 6, hs = n & 63;
    const float* W = (m == 0) ? Wq : ((m == 1) ? Wk : Wv);
    float v = rna_tf32_f(W[k * HS + hs]);
    int g = k >> 3, q = k & 3, half = (k >> 2) & 1;
    WpG[((g * 4 + q) * 192 + n) * 2 + half] = v;
}

// ============================================================================
// Phase 1 (device fn): one 128-row QKV tile, 1xTF32, double-buffered.
// ============================================================================
#define ASTRIDE 40
#define BP      392
#define AOFFB 0
#define BOFFB 20480
#define QBUF  46080
#define FUSED_SMEM (2 * QBUF)       // 92160 B

__device__ void qkv_tile(char* sm, uint32_t sb, const float* __restrict__ X,
                         size_t row0, int tid, int lane, int w, int gid, int tg)
{
    const int m0 = (w >> 1) * 32;
    const int n0 = (w & 1) * 96;

    auto stage = [&](int c, int buf) {
        const int k0 = c * 32;
        const uint32_t base = sb + buf * QBUF;
#pragma unroll
        for (int it = 0; it < 4; it++) {
            int i  = tid + 256 * it;
            int r  = i >> 3;
            int c4 = (i & 7) << 2;
            cp16(base + AOFFB + (uint32_t)(r * ASTRIDE + c4) * 4,
                 &X[(row0 + r) * CC + k0 + c4]);
        }
#pragma unroll
        for (int it = 0; it < 6; it++) {
            int i  = tid + 256 * it;
            int r  = i / 96;
            int cw = (i % 96) << 2;
            cp16(base + BOFFB + (uint32_t)(r * BP + cw) * 4,
                 &WpG[(size_t)(c * 16 + r) * 384 + cw]);
        }
        CP_COMMIT();
    };

    float acc[2][12][4] = {};

    stage(0, 0);
#pragma unroll 1
    for (int c = 0; c < 12; c++) {
        if (c < 11) { stage(c + 1, (c + 1) & 1); CP_WAIT1(); } else { CP_WAIT0(); }
        __syncthreads();
        const int buf = c & 1;
        const uint32_t* A  = reinterpret_cast<const uint32_t*>(sm + buf * QBUF + AOFFB);
        const float2*  Bp  = reinterpret_cast<const float2*>(sm + buf * QBUF + BOFFB);

#pragma unroll
        for (int ks = 0; ks < 4; ks++) {
            const int kc = ks * 8 + tg;
            uint32_t a[2][4];
#pragma unroll
            for (int mt = 0; mt < 2; mt++) {
                const int r = m0 + mt * 16 + gid;
                a[mt][0] = rna_tf32(A[r * ASTRIDE + kc]);
                a[mt][1] = rna_tf32(A[(r + 8) * ASTRIDE + kc]);
                a[mt][2] = rna_tf32(A[r * ASTRIDE + kc + 4]);
                a[mt][3] = rna_tf32(A[(r + 8) * ASTRIDE + kc + 4]);
            }
            const float2* brow = &Bp[(ks * 4 + tg) * (BP / 2)];
#pragma unroll
            for (int nt = 0; nt < 12; nt++) {
                const int col = n0 + nt * 8 + gid;
                float2 bb = brow[col];
                uint32_t b0 = __float_as_uint(bb.x);
                uint32_t b1 = __float_as_uint(bb.y);
                mma16808t(acc[0][nt], a[0][0], a[0][1], a[0][2], a[0][3], b0, b1);
                mma16808t(acc[1][nt], a[1][0], a[1][1], a[1][2], a[1][3], b0, b1);
            }
        }
        __syncthreads();
    }

    // epilogue
#pragma unroll
    for (int nt = 0; nt < 12; nt++) {
        const int colg = n0 + nt * 8 + 2 * tg;
        const int mat  = colg >> 6;
        const int hs0  = colg & 63;
#pragma unroll
        for (int mt = 0; mt < 2; mt++) {
            const size_t rowA = row0 + m0 + mt * 16 + gid;
            const size_t rowB = rowA + 8;
            const float* cc = acc[mt][nt];
            if (mat == 2) {
                const size_t baseA = (rowA >> 8) * (size_t)(HS * TT) + pk8((int)(rowA & 255));
                const size_t baseB = (rowB >> 8) * (size_t)(HS * TT) + pk8((int)(rowB & 255));
                VtfG[baseA + (size_t)hs0 * TT]       = rna_tf32_f(cc[0]);
                VtfG[baseA + (size_t)(hs0 + 1) * TT] = rna_tf32_f(cc[1]);
                VtfG[baseB + (size_t)hs0 * TT]       = rna_tf32_f(cc[2]);
                VtfG[baseB + (size_t)(hs0 + 1) * TT] = rna_tf32_f(cc[3]);
            } else if (mat == 0) {
                *reinterpret_cast<float2*>(&QfG[rowA * HS + hs0]) =
                    make_float2(rna_tf32_f(cc[0] * SCALE2), rna_tf32_f(cc[1] * SCALE2));
                *reinterpret_cast<float2*>(&QfG[rowB * HS + hs0]) =
                    make_float2(rna_tf32_f(cc[2] * SCALE2), rna_tf32_f(cc[3] * SCALE2));
            } else {
                const int p = pk8(hs0);
                KfG[rowA * HS + p]     = rna_tf32_f(cc[0]);
                KfG[rowA * HS + p + 2] = rna_tf32_f(cc[1]);
                KfG[rowB * HS + p]     = rna_tf32_f(cc[2]);
                KfG[rowB * HS + p + 2] = rna_tf32_f(cc[3]);
            }
        }
    }
}

// ============================================================================
// Phase 2 (device fn): attention for one query half of one batch.
// ============================================================================
#define KSTRIDE 72
#define KBYTES  (64 * KSTRIDE * 4)          // 18432
#define ABUF    (2 * KBYTES)                // 36864 (x2 buffers = 73728 <= FUSED_SMEM)

#define SCORE_TILE(nt) do {                                                  \
    float cc[4] = {0.f, 0.f, 0.f, 0.f};                                      \
    const float2* kr = reinterpret_cast<const float2*>(                      \
        &Ks[((nt) * 8 + gid) * KSTRIDE]);                                    \
    _Pragma("unroll")                                                        \
    for (int ks = 0; ks < 8; ks++) {                                         \
        float2 bb = kr[ks * 4 + tg];                                         \
        mma16808t(cc, a[ks][0], a[ks][1], a[ks][2], a[ks][3],                \
                  __float_as_uint(bb.x), __float_as_uint(bb.y));             \
    }                                                                        \
    s[(nt) * 4 + 0] = cc[0]; s[(nt) * 4 + 1] = cc[1];                        \
    s[(nt) * 4 + 2] = cc[2]; s[(nt) * 4 + 3] = cc[3];                        \
} while (0)

#define SCORE_MASK2(nt) do {                                                 \
    s[(nt) * 4 + 0] = -1e30f; s[(nt) * 4 + 1] = -1e30f;                      \
    s[(nt) * 4 + 2] = -1e30f; s[(nt) * 4 + 3] = -1e30f;                      \
    s[(nt) * 4 + 4] = -1e30f; s[(nt) * 4 + 5] = -1e30f;                      \
    s[(nt) * 4 + 6] = -1e30f; s[(nt) * 4 + 7] = -1e30f;                      \
} while (0)

#define PV_GROUP(g) do {                                                     \
    const int lb   = lane & ~3;                                              \
    const int srcA = lb | (tg >> 1);                                         \
    const int srcB = lb | 2 | (tg >> 1);                                     \
    float v00 = __shfl_sync(0xffffffffu, s[(g) * 4 + 0], srcA);              \
    float v01 = __shfl_sync(0xffffffffu, s[(g) * 4 + 1], srcA);              \
    float v10 = __shfl_sync(0xffffffffu, s[(g) * 4 + 2], srcA);              \
    float v11 = __shfl_sync(0xffffffffu, s[(g) * 4 + 3], srcA);              \
    float w00 = __shfl_sync(0xffffffffu, s[(g) * 4 + 0], srcB);              \
    float w01 = __shfl_sync(0xffffffffu, s[(g) * 4 + 1], srcB);              \
    float w10 = __shfl_sync(0xffffffffu, s[(g) * 4 + 2], srcB);              \
    float w11 = __shfl_sync(0xffffffffu, s[(g) * 4 + 3], srcB);              \
    const bool podd = (tg & 1);                                              \
    uint32_t pa0 = __float_as_uint(podd ? v01 : v00);                        \
    uint32_t pa1 = __float_as_uint(podd ? v11 : v10);                        \
    uint32_t pa2 = __float_as_uint(podd ? w01 : w00);                        \
    uint32_t pa3 = __float_as_uint(podd ? w11 : w10);                        \
    _Pragma("unroll")                                                        \
    for (int hn = 0; hn < 8; hn++) {                                         \
        const float2* vr = reinterpret_cast<const float2*>(                  \
            &Vs[(hn * 8 + gid) * KSTRIDE]);                                  \
        float2 bb = vr[(g) * 4 + tg];                                        \
        mma16808t(&O[hn * 4], pa0, pa1, pa2, pa3,                            \
                  __float_as_uint(bb.x), __float_as_uint(bb.y));             \
    }                                                                        \
} while (0)

__device__ void attn_half(char* sm, uint32_t sb, float* __restrict__ out,
                          int b, int half, int tid, int lane, int w, int gid, int tg)
{
    const int qb = half * 128 + w * 16;

    auto stage = [&](int c, int buf) {
        const int kn0 = c * 64;
        const uint32_t base = sb + buf * ABUF;
#pragma unroll
        for (int it = 0; it < 4; it++) {
            int i  = tid + 256 * it;
            int r  = i >> 4;
            int c4 = (i & 15) << 2;
            cp16(base + (uint32_t)(r * KSTRIDE + c4) * 4,
                 &KfG[((size_t)b * TT + kn0 + r) * HS + c4]);
        }
#pragma unroll
        for (int it = 0; it < 4; it++) {
            int i  = tid + 256 * it;
            int r  = i >> 4;
            int c4 = (i & 15) << 2;
            cp16(base + KBYTES + (uint32_t)(r * KSTRIDE + c4) * 4,
                 &VtfG[((size_t)b * HS + r) * TT + kn0 + c4]);
        }
        CP_COMMIT();
    };

    uint32_t a[8][4];
    {
        const float* q0 = &QfG[((size_t)b * TT + qb + gid) * HS];
        const float* q1 = q0 + 8 * HS;
#pragma unroll
        for (int ks = 0; ks < 8; ks++) {
            a[ks][0] = __float_as_uint(q0[ks * 8 + tg]);
            a[ks][1] = __float_as_uint(q1[ks * 8 + tg]);
            a[ks][2] = __float_as_uint(q0[ks * 8 + tg + 4]);
            a[ks][3] = __float_as_uint(q1[ks * 8 + tg + 4]);
        }
    }

    float O[32];
#pragma unroll
    for (int i = 0; i < 32; i++) O[i] = 0.f;
    float mr0 = -1e30f, mr1 = -1e30f, l0 = 0.f, l1 = 0.f;

    const int nch = (half + 1) * 2;
    stage(0, 0);
#pragma unroll 1
    for (int c = 0; c < nch; c++) {
        if (c < nch - 1) { stage(c + 1, (c + 1) & 1); CP_WAIT1(); } else { CP_WAIT0(); }
        __syncthreads();
        const int kn0 = c * 64;
        const int buf = c & 1;
        const float* Ks = reinterpret_cast<const float*>(sm + buf * ABUF);
        const float* Vs = reinterpret_cast<const float*>(sm + buf * ABUF + KBYTES);

        if (kn0 <= qb) {
            const bool diag = (kn0 + 63 > qb);
            const int ntmax = diag ? (((qb + 15 - kn0) >> 3) + 1) : 8;
            float s[32];

            if (!diag) {
                SCORE_TILE(0); SCORE_TILE(1); SCORE_TILE(2); SCORE_TILE(3);
                SCORE_TILE(4); SCORE_TILE(5); SCORE_TILE(6); SCORE_TILE(7);
            } else {
                SCORE_TILE(0); SCORE_TILE(1);
                if (ntmax > 2) { SCORE_TILE(2); SCORE_TILE(3); } else { SCORE_MASK2(2); }
                if (ntmax > 4) { SCORE_TILE(4); SCORE_TILE(5); } else { SCORE_MASK2(4); }
                if (ntmax > 6) { SCORE_TILE(6); SCORE_TILE(7); } else { SCORE_MASK2(6); }
                const int r0 = qb + gid, r1 = qb + 8 + gid;
#pragma unroll
                for (int nt = 0; nt < 8; nt++) {
                    const int col = kn0 + nt * 8 + 2 * tg;
                    if (col     > r0) s[nt * 4 + 0] = -1e30f;
                    if (col + 1 > r0) s[nt * 4 + 1] = -1e30f;
                    if (col     > r1) s[nt * 4 + 2] = -1e30f;
                    if (col + 1 > r1) s[nt * 4 + 3] = -1e30f;
                }
            }

            float c0m = -1e30f, c1m = -1e30f;
#pragma unroll
            for (int nt = 0; nt < 8; nt++) {
                c0m = fmaxf(c0m, fmaxf(s[nt * 4 + 0], s[nt * 4 + 1]));
                c1m = fmaxf(c1m, fmaxf(s[nt * 4 + 2], s[nt * 4 + 3]));
            }
            c0m = fmaxf(c0m, __shfl_xor_sync(0xffffffffu, c0m, 1));
            c0m = fmaxf(c0m, __shfl_xor_sync(0xffffffffu, c0m, 2));
            c1m = fmaxf(c1m, __shfl_xor_sync(0xffffffffu, c1m, 1));
            c1m = fmaxf(c1m, __shfl_xor_sync(0xffffffffu, c1m, 2));
            const float mn0 = fmaxf(mr0, c0m), mn1 = fmaxf(mr1, c1m);
            const float corr0 = ex2f(mr0 - mn0), corr1 = ex2f(mr1 - mn1);
            mr0 = mn0; mr1 = mn1;

            float sum0 = 0.f, sum1 = 0.f;
#pragma unroll
            for (int nt = 0; nt < 8; nt++) {
                float p0 = ex2f(s[nt * 4 + 0] - mn0);
                float p1 = ex2f(s[nt * 4 + 1] - mn0);
                float p2 = ex2f(s[nt * 4 + 2] - mn1);
                float p3 = ex2f(s[nt * 4 + 3] - mn1);
                s[nt * 4 + 0] = p0; s[nt * 4 + 1] = p1;
                s[nt * 4 + 2] = p2; s[nt * 4 + 3] = p3;
                sum0 += p0 + p1; sum1 += p2 + p3;
            }
            sum0 += __shfl_xor_sync(0xffffffffu, sum0, 1);
            sum0 += __shfl_xor_sync(0xffffffffu, sum0, 2);
            sum1 += __shfl_xor_sync(0xffffffffu, sum1, 1);
            sum1 += __shfl_xor_sync(0xffffffffu, sum1, 2);
            l0 = l0 * corr0 + sum0;
            l1 = l1 * corr1 + sum1;
#pragma unroll
            for (int hn = 0; hn < 8; hn++) {
                O[hn * 4 + 0] *= corr0; O[hn * 4 + 1] *= corr0;
                O[hn * 4 + 2] *= corr1; O[hn * 4 + 3] *= corr1;
            }

            if (!diag) {
                PV_GROUP(0); PV_GROUP(1); PV_GROUP(2); PV_GROUP(3);
                PV_GROUP(4); PV_GROUP(5); PV_GROUP(6); PV_GROUP(7);
            } else {
                PV_GROUP(0); PV_GROUP(1);
                if (ntmax > 2) { PV_GROUP(2); PV_GROUP(3); }
                if (ntmax > 4) { PV_GROUP(4); PV_GROUP(5); }
                if (ntmax > 6) { PV_GROUP(6); PV_GROUP(7); }
            }
        }
        __syncthreads();
    }

    const float i0 = 1.f / l0, i1 = 1.f / l1;
    float* o0 = out + ((size_t)b * TT + qb + gid) * HS;
    float* o1 = o0 + 8 * HS;
#pragma unroll
    for (int hn = 0; hn < 8; hn++) {
        *reinterpret_cast<float2*>(&o0[hn * 8 + 2 * tg]) =
            make_float2(O[hn * 4 + 0] * i0, O[hn * 4 + 1] * i0);
        *reinterpret_cast<float2*>(&o1[hn * 8 + 2 * tg]) =
            make_float2(O[hn * 4 + 2] * i1, O[hn * 4 + 3] * i1);
    }
}

// ============================================================================
// Fused kernel: one CTA per batch. Phase 1 = two QKV tiles; phase 2 = both
// attention halves. Same-CTA global write->syncthreads->read is safe.
// ============================================================================
__global__ __launch_bounds__(256, 2)
void fused_head(const float* __restrict__ X, float* __restrict__ out)
{
    extern __shared__ char sm[];
    const uint32_t sb = smem_u32(sm);
    const int b    = blockIdx.x;
    const int tid  = threadIdx.x;
    const int lane = tid & 31;
    const int w    = tid >> 5;
    const int gid  = lane >> 2;
    const int tg   = lane & 3;

    // Phase 1: QKV for this batch (rows b*256 .. b*256+255)
    qkv_tile(sm, sb, X, (size_t)b * TT,       tid, lane, w, gid, tg);
    qkv_tile(sm, sb, X, (size_t)b * TT + 128, tid, lane, w, gid, tg);
    __syncthreads();

    // Phase 2: attention, both query halves
    attn_half(sm, sb, out, b, 0, tid, lane, w, gid, tg);
    __syncthreads();
    attn_half(sm, sb, out, b, 1, tid, lane, w, gid, tg);
}

// ============================================================================
extern "C" void kernel_launch(void* const* d_in, const int* in_sizes, int n_in,
                              void* d_out, int out_size)
{
    const float* x  = (const float*)d_in[0];
    const float* Wq = (const float*)d_in[1];
    const float* Wk = (const float*)d_in[2];
    const float* Wv = (const float*)d_in[3];
    float* out = (float*)d_out;

    (void)in_sizes; (void)n_in; (void)out_size;

    prep_w<<<(384 * 192 + 255) / 256, 256>>>(Wq, Wk, Wv);

    cudaFuncSetAttribute(fused_head, cudaFuncAttributeMaxDynamicSharedMemorySize, FUSED_SMEM);
    fused_head<<<BB, 256, FUSED_SMEM>>>(x, out);
}

// round 17
// speedup vs baseline: 1.0011x; 1.0011x over previous
#include <cuda_runtime.h>
#include <cuda_bf16.h>
#include <cstdint>

#define BB   1024
#define TT   256
#define CC   384
#define HS   64

// Scratch (device globals: allocation-free). Layouts as in R13:
// QfG: Q*SCALE2, tf32-RNA, row-major. KfG: hs pair-packed within 8.
// VtfG: V^T with t pair-packed within 8. WpG: W pair-packed.
__device__ __align__(16) float QfG[BB * TT * HS];
__device__ __align__(16) float KfG[BB * TT * HS];
__device__ __align__(16) float VtfG[BB * HS * TT];
__device__ __align__(16) float WpG[384 * 192];

// ---------------- helpers ----------------
__device__ __forceinline__ uint32_t smem_u32(const void* p) {
    uint32_t a;
    asm("{ .reg .u64 t; cvta.to.shared.u64 t, %1; cvt.u32.u64 %0, t; }" : "=r"(a) : "l"(p));
    return a;
}
__device__ __forceinline__ void cp16(uint32_t dst, const void* src) {
    asm volatile("cp.async.ca.shared.global [%0], [%1], 16;" :: "r"(dst), "l"(src) : "memory");
}
#define CP_COMMIT() asm volatile("cp.async.commit_group;" ::: "memory")
#define CP_WAIT1()  asm volatile("cp.async.wait_group 1;" ::: "memory")
#define CP_WAIT0()  asm volatile("cp.async.wait_group 0;" ::: "memory")

__device__ __forceinline__ uint32_t rna_tf32(uint32_t x) {
    uint32_t r;
    asm("cvt.rna.tf32.f32 %0, %1;" : "=r"(r) : "r"(x));
    return r;
}
__device__ __forceinline__ float rna_tf32_f(float x) {
    float r;
    asm("cvt.rna.tf32.f32 %0, %1;" : "=f"(r) : "f"(x));
    return r;
}
__device__ __forceinline__ float ex2f(float x) {
    float r;
    asm("ex2.approx.f32 %0, %1;" : "=f"(r) : "f"(x));
    return r;
}
#define SCALE2 0.18033688f   // 0.125 * log2(e)

__device__ __forceinline__ int pk8(int h) {
    return (h & ~7) + (h & 3) * 2 + ((h >> 2) & 1);
}

__device__ __forceinline__ void mma16808t(float* c,
                                          uint32_t a0, uint32_t a1, uint32_t a2, uint32_t a3,
                                          uint32_t b0, uint32_t b1) {
    asm volatile(
        "mma.sync.aligned.m16n8k8.row.col.f32.tf32.tf32.f32 "
        "{%0,%1,%2,%3}, {%4,%5,%6,%7}, {%8,%9}, {%0,%1,%2,%3};"
        : "+f"(c[0]), "+f"(c[1]), "+f"(c[2]), "+f"(c[3])
        : "r"(a0), "r"(a1), "r"(a2), "r"(a3), "r"(b0), "r"(b1));
}

// ============================================================================
// Kernel 0: pack W pairs (tf32-RNA): ((k>>3)*4+(k&3))*192+n, half=(k>>2)&1.
// ============================================================================
__global__ void prep_w(const float* __restrict__ Wq,
                       const float* __restrict__ Wk,
                       const float* __restrict__ Wv)
{
    int idx = blockIdx.x * blockDim.x + threadIdx.x;
    if (idx >= 384 * 192) return;
    int k = idx / 192;
    int n = idx % 192;
    int m = n >> 6, hs = n & 63;
    const float* W = (m == 0) ? Wq : ((m == 1) ? Wk : Wv);
    float v = rna_tf32_f(W[k * HS + hs]);
    int g = k >> 3, q = k & 3, half = (k >> 2) & 1;
    WpG[((g * 4 + q) * 192 + n) * 2 + half] = v;
}

// ============================================================================
// Phase 1 (device fn): one 128-row QKV tile, 1xTF32, double-buffered.
// ============================================================================
#define ASTRIDE 40
#define BP      392
#define AOFFB 0
#define BOFFB 20480
#define QBUF  46080
#define FUSED_SMEM (2 * QBUF)       // 92160 B

__device__ void qkv_tile(char* sm, uint32_t sb, const float* __restrict__ X,
                         size_t row0, int tid, int lane, int w, int gid, int tg)
{
    const int m0 = (w >> 1) * 32;
    const int n0 = (w & 1) * 96;

    auto stage = [&](int c, int buf) {
        const int k0 = c * 32;
        const uint32_t base = sb + buf * QBUF;
#pragma unroll
        for (int it = 0; it < 4; it++) {
            int i  = tid + 256 * it;
            int r  = i >> 3;
            int c4 = (i & 7) << 2;
            cp16(base + AOFFB + (uint32_t)(r * ASTRIDE + c4) * 4,
                 &X[(row0 + r) * CC + k0 + c4]);
        }
#pragma unroll
        for (int it = 0; it < 6; it++) {
            int i  = tid + 256 * it;
            int r  = i / 96;
            int cw = (i % 96) << 2;
            cp16(base + BOFFB + (uint32_t)(r * BP + cw) * 4,
                 &WpG[(size_t)(c * 16 + r) * 384 + cw]);
        }
        CP_COMMIT();
    };

    float acc[2][12][4] = {};

    stage(0, 0);
#pragma unroll 1
    for (int c = 0; c < 12; c++) {
        if (c < 11) { stage(c + 1, (c + 1) & 1); CP_WAIT1(); } else { CP_WAIT0(); }
        __syncthreads();
        const int buf = c & 1;
        const uint32_t* A  = reinterpret_cast<const uint32_t*>(sm + buf * QBUF + AOFFB);
        const float2*  Bp  = reinterpret_cast<const float2*>(sm + buf * QBUF + BOFFB);

#pragma unroll
        for (int ks = 0; ks < 4; ks++) {
            const int kc = ks * 8 + tg;
            uint32_t a[2][4];
#pragma unroll
            for (int mt = 0; mt < 2; mt++) {
                const int r = m0 + mt * 16 + gid;
                a[mt][0] = rna_tf32(A[r * ASTRIDE + kc]);
                a[mt][1] = rna_tf32(A[(r + 8) * ASTRIDE + kc]);
                a[mt][2] = rna_tf32(A[r * ASTRIDE + kc + 4]);
                a[mt][3] = rna_tf32(A[(r + 8) * ASTRIDE + kc + 4]);
            }
            const float2* brow = &Bp[(ks * 4 + tg) * (BP / 2)];
#pragma unroll
            for (int nt = 0; nt < 12; nt++) {
                const int col = n0 + nt * 8 + gid;
                float2 bb = brow[col];
                uint32_t b0 = __float_as_uint(bb.x);
                uint32_t b1 = __float_as_uint(bb.y);
                mma16808t(acc[0][nt], a[0][0], a[0][1], a[0][2], a[0][3], b0, b1);
                mma16808t(acc[1][nt], a[1][0], a[1][1], a[1][2], a[1][3], b0, b1);
            }
        }
        __syncthreads();
    }

    // epilogue
#pragma unroll
    for (int nt = 0; nt < 12; nt++) {
        const int colg = n0 + nt * 8 + 2 * tg;
        const int mat  = colg >> 6;
        const int hs0  = colg & 63;
#pragma unroll
        for (int mt = 0; mt < 2; mt++) {
            const size_t rowA = row0 + m0 + mt * 16 + gid;
            const size_t rowB = rowA + 8;
            const float* cc = acc[mt][nt];
            if (mat == 2) {
                const size_t baseA = (rowA >> 8) * (size_t)(HS * TT) + pk8((int)(rowA & 255));
                const size_t baseB = (rowB >> 8) * (size_t)(HS * TT) + pk8((int)(rowB & 255));
                VtfG[baseA + (size_t)hs0 * TT]       = rna_tf32_f(cc[0]);
                VtfG[baseA + (size_t)(hs0 + 1) * TT] = rna_tf32_f(cc[1]);
                VtfG[baseB + (size_t)hs0 * TT]       = rna_tf32_f(cc[2]);
                VtfG[baseB + (size_t)(hs0 + 1) * TT] = rna_tf32_f(cc[3]);
            } else if (mat == 0) {
                *reinterpret_cast<float2*>(&QfG[rowA * HS + hs0]) =
                    make_float2(rna_tf32_f(cc[0] * SCALE2), rna_tf32_f(cc[1] * SCALE2));
                *reinterpret_cast<float2*>(&QfG[rowB * HS + hs0]) =
                    make_float2(rna_tf32_f(cc[2] * SCALE2), rna_tf32_f(cc[3] * SCALE2));
            } else {
                const int p = pk8(hs0);
                KfG[rowA * HS + p]     = rna_tf32_f(cc[0]);
                KfG[rowA * HS + p + 2] = rna_tf32_f(cc[1]);
                KfG[rowB * HS + p]     = rna_tf32_f(cc[2]);
                KfG[rowB * HS + p + 2] = rna_tf32_f(cc[3]);
            }
        }
    }
}

// ============================================================================
// Phase 2 (device fn): attention for one query half of one batch.
// ============================================================================
#define KSTRIDE 72
#define KBYTES  (64 * KSTRIDE * 4)          // 18432
#define ABUF    (2 * KBYTES)                // 36864 (x2 buffers = 73728 <= FUSED_SMEM)

#define SCORE_TILE(nt) do {                                                  \
    float cc[4] = {0.f, 0.f, 0.f, 0.f};                                      \
    const float2* kr = reinterpret_cast<const float2*>(                      \
        &Ks[((nt) * 8 + gid) * KSTRIDE]);                                    \
    _Pragma("unroll")                                                        \
    for (int ks = 0; ks < 8; ks++) {                                         \
        float2 bb = kr[ks * 4 + tg];                                         \
        mma16808t(cc, a[ks][0], a[ks][1], a[ks][2], a[ks][3],                \
                  __float_as_uint(bb.x), __float_as_uint(bb.y));             \
    }                                                                        \
    s[(nt) * 4 + 0] = cc[0]; s[(nt) * 4 + 1] = cc[1];                        \
    s[(nt) * 4 + 2] = cc[2]; s[(nt) * 4 + 3] = cc[3];                        \
} while (0)

#define SCORE_MASK2(nt) do {                                                 \
    s[(nt) * 4 + 0] = -1e30f; s[(nt) * 4 + 1] = -1e30f;                      \
    s[(nt) * 4 + 2] = -1e30f; s[(nt) * 4 + 3] = -1e30f;                      \
    s[(nt) * 4 + 4] = -1e30f; s[(nt) * 4 + 5] = -1e30f;                      \
    s[(nt) * 4 + 6] = -1e30f; s[(nt) * 4 + 7] = -1e30f;                      \
} while (0)

#define PV_GROUP(g) do {                                                     \
    const int lb   = lane & ~3;                                              \
    const int srcA = lb | (tg >> 1);                                         \
    const int srcB = lb | 2 | (tg >> 1);                                     \
    float v00 = __shfl_sync(0xffffffffu, s[(g) * 4 + 0], srcA);              \
    float v01 = __shfl_sync(0xffffffffu, s[(g) * 4 + 1], srcA);              \
    float v10 = __shfl_sync(0xffffffffu, s[(g) * 4 + 2], srcA);              \
    float v11 = __shfl_sync(0xffffffffu, s[(g) * 4 + 3], srcA);              \
    float w00 = __shfl_sync(0xffffffffu, s[(g) * 4 + 0], srcB);              \
    float w01 = __shfl_sync(0xffffffffu, s[(g) * 4 + 1], srcB);              \
    float w10 = __shfl_sync(0xffffffffu, s[(g) * 4 + 2], srcB);              \
    float w11 = __shfl_sync(0xffffffffu, s[(g) * 4 + 3], srcB);              \
    const bool podd = (tg & 1);                                              \
    uint32_t pa0 = __float_as_uint(podd ? v01 : v00);                        \
    uint32_t pa1 = __float_as_uint(podd ? v11 : v10);                        \
    uint32_t pa2 = __float_as_uint(podd ? w01 : w00);                        \
    uint32_t pa3 = __float_as_uint(podd ? w11 : w10);                        \
    _Pragma("unroll")                                                        \
    for (int hn = 0; hn < 8; hn++) {                                         \
        const float2* vr = reinterpret_cast<const float2*>(                  \
            &Vs[(hn * 8 + gid) * KSTRIDE]);                                  \
        float2 bb = vr[(g) * 4 + tg];                                        \
        mma16808t(&O[hn * 4], pa0, pa1, pa2, pa3,                            \
                  __float_as_uint(bb.x), __float_as_uint(bb.y));             \
    }                                                                        \
} while (0)

__device__ void attn_half(char* sm, uint32_t sb, float* __restrict__ out,
                          int b, int half, int tid, int lane, int w, int gid, int tg)
{
    const int qb = half * 128 + w * 16;

    auto stage = [&](int c, int buf) {
        const int kn0 = c * 64;
        const uint32_t base = sb + buf * ABUF;
#pragma unroll
        for (int it = 0; it < 4; it++) {
            int i  = tid + 256 * it;
            int r  = i >> 4;
            int c4 = (i & 15) << 2;
            cp16(base + (uint32_t)(r * KSTRIDE + c4) * 4,
                 &KfG[((size_t)b * TT + kn0 + r) * HS + c4]);
        }
#pragma unroll
        for (int it = 0; it < 4; it++) {
            int i  = tid + 256 * it;
            int r  = i >> 4;
            int c4 = (i & 15) << 2;
            cp16(base + KBYTES + (uint32_t)(r * KSTRIDE + c4) * 4,
                 &VtfG[((size_t)b * HS + r) * TT + kn0 + c4]);
        }
        CP_COMMIT();
    };

    uint32_t a[8][4];
    {
        const float* q0 = &QfG[((size_t)b * TT + qb + gid) * HS];
        const float* q1 = q0 + 8 * HS;
#pragma unroll
        for (int ks = 0; ks < 8; ks++) {
            a[ks][0] = __float_as_uint(q0[ks * 8 + tg]);
            a[ks][1] = __float_as_uint(q1[ks * 8 + tg]);
            a[ks][2] = __float_as_uint(q0[ks * 8 + tg + 4]);
            a[ks][3] = __float_as_uint(q1[ks * 8 + tg + 4]);
        }
    }

    float O[32];
#pragma unroll
    for (int i = 0; i < 32; i++) O[i] = 0.f;
    float mr0 = -1e30f, mr1 = -1e30f, l0 = 0.f, l1 = 0.f;

    const int nch = (half + 1) * 2;
    stage(0, 0);
#pragma unroll 1
    for (int c = 0; c < nch; c++) {
        if (c < nch - 1) { stage(c + 1, (c + 1) & 1); CP_WAIT1(); } else { CP_WAIT0(); }
        __syncthreads();
        const int kn0 = c * 64;
        const int buf = c & 1;
        const float* Ks = reinterpret_cast<const float*>(sm + buf * ABUF);
        const float* Vs = reinterpret_cast<const float*>(sm + buf * ABUF + KBYTES);

        if (kn0 <= qb) {
            const bool diag = (kn0 + 63 > qb);
            const int ntmax = diag ? (((qb + 15 - kn0) >> 3) + 1) : 8;
            float s[32];

            if (!diag) {
                SCORE_TILE(0); SCORE_TILE(1); SCORE_TILE(2); SCORE_TILE(3);
                SCORE_TILE(4); SCORE_TILE(5); SCORE_TILE(6); SCORE_TILE(7);
            } else {
                SCORE_TILE(0); SCORE_TILE(1);
                if (ntmax > 2) { SCORE_TILE(2); SCORE_TILE(3); } else { SCORE_MASK2(2); }
                if (ntmax > 4) { SCORE_TILE(4); SCORE_TILE(5); } else { SCORE_MASK2(4); }
                if (ntmax > 6) { SCORE_TILE(6); SCORE_TILE(7); } else { SCORE_MASK2(6); }
                const int r0 = qb + gid, r1 = qb + 8 + gid;
#pragma unroll
                for (int nt = 0; nt < 8; nt++) {
                    const int col = kn0 + nt * 8 + 2 * tg;
                    if (col     > r0) s[nt * 4 + 0] = -1e30f;
                    if (col + 1 > r0) s[nt * 4 + 1] = -1e30f;
                    if (col     > r1) s[nt * 4 + 2] = -1e30f;
                    if (col + 1 > r1) s[nt * 4 + 3] = -1e30f;
                }
            }

            float c0m = -1e30f, c1m = -1e30f;
#pragma unroll
            for (int nt = 0; nt < 8; nt++) {
                c0m = fmaxf(c0m, fmaxf(s[nt * 4 + 0], s[nt * 4 + 1]));
                c1m = fmaxf(c1m, fmaxf(s[nt * 4 + 2], s[nt * 4 + 3]));
            }
            c0m = fmaxf(c0m, __shfl_xor_sync(0xffffffffu, c0m, 1));
            c0m = fmaxf(c0m, __shfl_xor_sync(0xffffffffu, c0m, 2));
            c1m = fmaxf(c1m, __shfl_xor_sync(0xffffffffu, c1m, 1));
            c1m = fmaxf(c1m, __shfl_xor_sync(0xffffffffu, c1m, 2));
            const float mn0 = fmaxf(mr0, c0m), mn1 = fmaxf(mr1, c1m);
            const float corr0 = ex2f(mr0 - mn0), corr1 = ex2f(mr1 - mn1);
            mr0 = mn0; mr1 = mn1;

            float sum0 = 0.f, sum1 = 0.f;
#pragma unroll
            for (int nt = 0; nt < 8; nt++) {
                float p0 = ex2f(s[nt * 4 + 0] - mn0);
                float p1 = ex2f(s[nt * 4 + 1] - mn0);
                float p2 = ex2f(s[nt * 4 + 2] - mn1);
                float p3 = ex2f(s[nt * 4 + 3] - mn1);
                s[nt * 4 + 0] = p0; s[nt * 4 + 1] = p1;
                s[nt * 4 + 2] = p2; s[nt * 4 + 3] = p3;
                sum0 += p0 + p1; sum1 += p2 + p3;
            }
            sum0 += __shfl_xor_sync(0xffffffffu, sum0, 1);
            sum0 += __shfl_xor_sync(0xffffffffu, sum0, 2);
            sum1 += __shfl_xor_sync(0xffffffffu, sum1, 1);
            sum1 += __shfl_xor_sync(0xffffffffu, sum1, 2);
            l0 = l0 * corr0 + sum0;
            l1 = l1 * corr1 + sum1;
#pragma unroll
            for (int hn = 0; hn < 8; hn++) {
                O[hn * 4 + 0] *= corr0; O[hn * 4 + 1] *= corr0;
                O[hn * 4 + 2] *= corr1; O[hn * 4 + 3] *= corr1;
            }

            if (!diag) {
                PV_GROUP(0); PV_GROUP(1); PV_GROUP(2); PV_GROUP(3);
                PV_GROUP(4); PV_GROUP(5); PV_GROUP(6); PV_GROUP(7);
            } else {
                PV_GROUP(0); PV_GROUP(1);
                if (ntmax > 2) { PV_GROUP(2); PV_GROUP(3); }
                if (ntmax > 4) { PV_GROUP(4); PV_GROUP(5); }
                if (ntmax > 6) { PV_GROUP(6); PV_GROUP(7); }
            }
        }
        __syncthreads();
    }

    const float i0 = 1.f / l0, i1 = 1.f / l1;
    float* o0 = out + ((size_t)b * TT + qb + gid) * HS;
    float* o1 = o0 + 8 * HS;
#pragma unroll
    for (int hn = 0; hn < 8; hn++) {
        *reinterpret_cast<float2*>(&o0[hn * 8 + 2 * tg]) =
            make_float2(O[hn * 4 + 0] * i0, O[hn * 4 + 1] * i0);
        *reinterpret_cast<float2*>(&o1[hn * 8 + 2 * tg]) =
            make_float2(O[hn * 4 + 2] * i1, O[hn * 4 + 3] * i1);
    }
}

// ============================================================================
// Fused kernel: one CTA per batch. Phase 1 = two QKV tiles; phase 2 = both
// attention halves. Same-CTA global write->syncthreads->read is safe.
// ============================================================================
__global__ __launch_bounds__(256, 2)
void fused_head(const float* __restrict__ X, float* __restrict__ out)
{
    extern __shared__ char sm[];
    const uint32_t sb = smem_u32(sm);
    const int b    = blockIdx.x;
    const int tid  = threadIdx.x;
    const int lane = tid & 31;
    const int w    = tid >> 5;
    const int gid  = lane >> 2;
    const int tg   = lane & 3;

    // Phase 1: QKV for this batch (rows b*256 .. b*256+255)
    qkv_tile(sm, sb, X, (size_t)b * TT,       tid, lane, w, gid, tg);
    qkv_tile(sm, sb, X, (size_t)b * TT + 128, tid, lane, w, gid, tg);
    __syncthreads();

    // Phase 2: attention, both query halves
    attn_half(sm, sb, out, b, 0, tid, lane, w, gid, tg);
    __syncthreads();
    attn_half(sm, sb, out, b, 1, tid, lane, w, gid, tg);
}

// ============================================================================
extern "C" void kernel_launch(void* const* d_in, const int* in_sizes, int n_in,
                              void* d_out, int out_size)
{
    const float* x  = (const float*)d_in[0];
    const float* Wq = (const float*)d_in[1];
    const float* Wk = (const float*)d_in[2];
    const float* Wv = (const float*)d_in[3];
    float* out = (float*)d_out;

    (void)in_sizes; (void)n_in; (void)out_size;

    prep_w<<<(384 * 192 + 255) / 256, 256>>>(Wq, Wk, Wv);

    cudaFuncSetAttribute(fused_head, cudaFuncAttributeMaxDynamicSharedMemorySize, FUSED_SMEM);
    fused_head<<<BB, 256, FUSED_SMEM>>>(x, out);
}